// round 1
// baseline (speedup 1.0000x reference)
#include <cuda_runtime.h>

#define Bc 4
#define Hc 16
#define Sc 4096
#define Dc 64
#define BHc (Bc*Hc)        // 64
#define NCHUNK 8
#define CHUNK (Sc/NCHUNK)  // 512
#define TS 32

// Scratch (allocation-free per harness rules)
__device__ float g_pKV[NCHUNK][BHc][Dc*Dc];  // partial KV per S-chunk
__device__ float g_pKs[NCHUNK][BHc][Dc];     // partial Ksum per S-chunk
__device__ float g_KV[BHc][Dc*Dc];           // reduced KV
__device__ float g_Ks[BHc][Dc];              // reduced Ksum

typedef unsigned long long u64;

__device__ __forceinline__ u64 pack2(float lo, float hi){
    u64 r; asm("mov.b64 %0, {%1,%2};" : "=l"(r) : "f"(lo), "f"(hi)); return r;
}
__device__ __forceinline__ void unpack2(u64 v, float &lo, float &hi){
    asm("mov.b64 {%0,%1}, %2;" : "=f"(lo), "=f"(hi) : "l"(v));
}
// packed dual-fp32 FMA (FFMA2 in SASS; only reachable via PTX fma.rn.f32x2)
__device__ __forceinline__ void fma2(u64 &d, u64 a, u64 b){
    asm("fma.rn.f32x2 %0, %1, %2, %0;" : "+l"(d) : "l"(a), "l"(b));
}
// elu(x)+1 feature map
__device__ __forceinline__ float feat(float x){
    return x > 0.f ? x + 1.f : __expf(x);
}

// ---------------------------------------------------------------------------
// Phase 1: partial KV[d][e] = sum_s Kf[s][d]*V[s][e], partial Ksum[d]
// grid (BHc, NCHUNK), 256 threads. Each thread owns a 4(d)x4(e) tile of KV,
// stored as 8 f32x2 accumulators (pairs over e).
// ---------------------------------------------------------------------------
__global__ __launch_bounds__(256) void phase1_kernel(const float* __restrict__ K,
                                                     const float* __restrict__ V,
                                                     const float* __restrict__ mask){
    __shared__ float sK[TS][Dc];
    __shared__ float sV[TS][Dc];

    const int bh = blockIdx.x, ch = blockIdx.y;
    const int tid = threadIdx.x;
    const float* Kp = K    + ((size_t)bh*Sc + (size_t)ch*CHUNK)*Dc;
    const float* Vp = V    + ((size_t)bh*Sc + (size_t)ch*CHUNK)*Dc;
    const float* Mp = mask + (size_t)bh*Sc + (size_t)ch*CHUNK;

    const int tx = tid & 15, ty = tid >> 4;
    const int e0 = tx*4, d0 = ty*4;

    u64 acc[4][2];
    #pragma unroll
    for (int i=0;i<4;i++){ acc[i][0]=pack2(0.f,0.f); acc[i][1]=pack2(0.f,0.f); }
    float ks = 0.f; // only meaningful for tid < 64 (warps 0-1)

    const int lr = tid >> 4;        // load row base (0..15)
    const int lc = (tid & 15) * 4;  // load col

    for (int st = 0; st < CHUNK; st += TS){
        #pragma unroll
        for (int rr = 0; rr < TS; rr += 16){
            int r = lr + rr;
            int s = st + r;
            float m  = Mp[s];
            float4 k4 = *(const float4*)(Kp + (size_t)s*Dc + lc);
            float4 v4 = *(const float4*)(Vp + (size_t)s*Dc + lc);
            sK[r][lc+0] = feat(k4.x)*m;
            sK[r][lc+1] = feat(k4.y)*m;
            sK[r][lc+2] = feat(k4.z)*m;
            sK[r][lc+3] = feat(k4.w)*m;
            *(float4*)&sV[r][lc] = v4;
        }
        __syncthreads();

        #pragma unroll 8
        for (int s = 0; s < TS; s++){
            float4 kf = *(const float4*)&sK[s][d0];   // broadcast within warp
            float4 vv = *(const float4*)&sV[s][e0];
            u64 va = pack2(vv.x, vv.y);
            u64 vb = pack2(vv.z, vv.w);
            u64 k0 = pack2(kf.x, kf.x);
            u64 k1 = pack2(kf.y, kf.y);
            u64 k2 = pack2(kf.z, kf.z);
            u64 k3 = pack2(kf.w, kf.w);
            fma2(acc[0][0], k0, va); fma2(acc[0][1], k0, vb);
            fma2(acc[1][0], k1, va); fma2(acc[1][1], k1, vb);
            fma2(acc[2][0], k2, va); fma2(acc[2][1], k2, vb);
            fma2(acc[3][0], k3, va); fma2(acc[3][1], k3, vb);
        }

        if (tid < Dc){               // warps 0-1 only, no intra-warp divergence
            #pragma unroll 8
            for (int s = 0; s < TS; s++) ks += sK[s][tid];
        }
        __syncthreads();
    }

    float* outKV = g_pKV[ch][bh];
    #pragma unroll
    for (int i=0;i<4;i++){
        float r0,r1,r2,r3;
        unpack2(acc[i][0], r0, r1);
        unpack2(acc[i][1], r2, r3);
        float4 w = make_float4(r0,r1,r2,r3);
        *(float4*)(outKV + (d0+i)*Dc + e0) = w;
    }
    if (tid < Dc) g_pKs[ch][bh][tid] = ks;
}

// ---------------------------------------------------------------------------
// Reduce partials: g_KV = sum_ch g_pKV, g_Ks = sum_ch g_pKs
// ---------------------------------------------------------------------------
__global__ void reduce_kernel(){
    const int idx = blockIdx.x*blockDim.x + threadIdx.x;
    const int nKV = BHc*Dc*Dc;
    if (idx < nKV){
        int bh = idx / (Dc*Dc), off = idx % (Dc*Dc);
        float s = 0.f;
        #pragma unroll
        for (int c = 0; c < NCHUNK; c++) s += g_pKV[c][bh][off];
        g_KV[bh][off] = s;
    } else {
        int j = idx - nKV;
        if (j < BHc*Dc){
            int bh = j / Dc, d = j % Dc;
            float s = 0.f;
            #pragma unroll
            for (int c = 0; c < NCHUNK; c++) s += g_pKs[c][bh][d];
            g_Ks[bh][d] = s;
        }
    }
}

// ---------------------------------------------------------------------------
// Phase 2: out[s][e] = Z[s] * sum_d Qf[s][d] * KV[d][e],  Z = 1/(Qf . Ksum)
// grid (BHc, Sc/64), 256 threads. 64 s-rows per CTA. 4(s)x4(e) thread tile.
// ---------------------------------------------------------------------------
__global__ __launch_bounds__(256) void phase2_kernel(const float* __restrict__ Q,
                                                     float* __restrict__ out){
    __shared__ float sKV[Dc][Dc];      // [d][e]
    __shared__ float sQt[Dc][Dc+1];    // [d][s_local], pad 1 vs transpose conflicts
    __shared__ float sKsum[Dc];
    __shared__ float sZ[64];

    const int bh = blockIdx.x, sb = blockIdx.y;
    const int tid = threadIdx.x;
    const float* Qp = Q + ((size_t)bh*Sc + (size_t)sb*64)*Dc;

    // load KV (flat, coalesced float4)
    {
        const float* kvp = g_KV[bh];
        float* dst = &sKV[0][0];
        #pragma unroll
        for (int i = tid; i < Dc*Dc/4; i += 256){
            *(float4*)(dst + i*4) = *(const float4*)(kvp + i*4);
        }
    }
    if (tid < Dc) sKsum[tid] = g_Ks[bh][tid];

    // load Q tile, apply feature map, store transposed
    {
        const int lr = tid >> 4, lc = (tid & 15)*4;
        #pragma unroll
        for (int rr = 0; rr < 64; rr += 16){
            int r = lr + rr;
            float4 q4 = *(const float4*)(Qp + (size_t)r*Dc + lc);
            sQt[lc+0][r] = feat(q4.x);
            sQt[lc+1][r] = feat(q4.y);
            sQt[lc+2][r] = feat(q4.z);
            sQt[lc+3][r] = feat(q4.w);
        }
    }
    __syncthreads();

    // normalization per s-row (64 threads)
    if (tid < 64){
        float z = 0.f;
        #pragma unroll 8
        for (int d = 0; d < Dc; d++) z += sQt[d][tid] * sKsum[d];
        sZ[tid] = 1.f / z;
    }
    __syncthreads();

    const int tx = tid & 15, ty = tid >> 4;
    const int e0 = tx*4, s0 = ty*4;

    u64 acc[4][2];
    #pragma unroll
    for (int i=0;i<4;i++){ acc[i][0]=pack2(0.f,0.f); acc[i][1]=pack2(0.f,0.f); }

    #pragma unroll 8
    for (int d = 0; d < Dc; d++){
        float q0 = sQt[d][s0+0];   // broadcast loads
        float q1 = sQt[d][s0+1];
        float q2 = sQt[d][s0+2];
        float q3 = sQt[d][s0+3];
        float4 kv = *(const float4*)&sKV[d][e0];
        u64 va = pack2(kv.x, kv.y);
        u64 vb = pack2(kv.z, kv.w);
        u64 a0 = pack2(q0, q0);
        u64 a1 = pack2(q1, q1);
        u64 a2 = pack2(q2, q2);
        u64 a3 = pack2(q3, q3);
        fma2(acc[0][0], a0, va); fma2(acc[0][1], a0, vb);
        fma2(acc[1][0], a1, va); fma2(acc[1][1], a1, vb);
        fma2(acc[2][0], a2, va); fma2(acc[2][1], a2, vb);
        fma2(acc[3][0], a3, va); fma2(acc[3][1], a3, vb);
    }

    #pragma unroll
    for (int i = 0; i < 4; i++){
        float z = sZ[s0+i];
        float r0,r1,r2,r3;
        unpack2(acc[i][0], r0, r1);
        unpack2(acc[i][1], r2, r3);
        float4 w = make_float4(r0*z, r1*z, r2*z, r3*z);
        *(float4*)(out + ((size_t)bh*Sc + (size_t)sb*64 + s0+i)*Dc + e0) = w;
    }
}

// ---------------------------------------------------------------------------
extern "C" void kernel_launch(void* const* d_in, const int* in_sizes, int n_in,
                              void* d_out, int out_size){
    const float* Q    = (const float*)d_in[0];
    const float* K    = (const float*)d_in[1];
    const float* V    = (const float*)d_in[2];
    const float* mask = (const float*)d_in[3];
    float* out = (float*)d_out;

    phase1_kernel<<<dim3(BHc, NCHUNK), 256>>>(K, V, mask);

    const int total = BHc*Dc*Dc + BHc*Dc;
    reduce_kernel<<<(total + 255)/256, 256>>>();

    phase2_kernel<<<dim3(BHc, Sc/64), 256>>>(Q, out);
}